// round 12
// baseline (speedup 1.0000x reference)
#include <cuda_runtime.h>
#include <cuda_bf16.h>
#include <cuda_fp16.h>
#include <math_constants.h>

#define NN 100000
#define EE 800000
#define GG 512
#define FF 64
#define OUTD 10

#define SCAN_CHUNK 1024
#define SCAN_BLOCKS ((NN + SCAN_CHUNK - 1) / SCAN_CHUNK)

// ---------------- scratch (device globals; no allocation allowed) -----------
__device__ int     d_cnt[NN];
__device__ float   d_loop[NN];
__device__ int     d_off[NN + 1];
__device__ int     d_cur[NN];
__device__ int     d_bsum[SCAN_BLOCKS];
__device__ int     d_csr_src[EE];
__device__ float   d_csr_ea[EE];
__device__ __half2 d_xph[NN * (FF / 2)];   // fp16 features for the gather path
__device__ float   d_h[NN * FF];
__device__ float   d_asrc[NN];
__device__ float   d_adst[NN];
__device__ float   d_cedge[2];

__device__ __forceinline__ float lrelu(float x) {
    return fmaxf(x, 0.2f * x);
}

// ---------------- zero + cedge (fused; single-warp, NO barrier) --------------
__global__ void zero_kernel(const float* __restrict__ We1, const float* __restrict__ ae1,
                            const float* __restrict__ We2, const float* __restrict__ ae2) {
    int i = blockIdx.x * blockDim.x + threadIdx.x;
    if (i < NN) { d_cnt[i] = 0; d_loop[i] = 0.f; }
    if (blockIdx.x == 0 && threadIdx.x < 32) {
        int t = threadIdx.x;
        float p1 = We1[t] * ae1[t] + We1[t + 32] * ae1[t + 32];
        float p2 = We2[t] * ae2[t] + We2[t + 32] * ae2[t + 32];
        #pragma unroll
        for (int o = 16; o > 0; o >>= 1) {
            p1 += __shfl_xor_sync(0xffffffff, p1, o);
            p2 += __shfl_xor_sync(0xffffffff, p2, o);
        }
        if (t == 0) { d_cedge[0] = p1; d_cedge[1] = p2; }
    }
}

// ---------------- CSR construction ------------------------------------------
__global__ void count_kernel(const int* __restrict__ ei, const float* __restrict__ ea) {
    int i = blockIdx.x * blockDim.x + threadIdx.x;
    if (i < EE) {
        int dd = ei[EE + i];
        atomicAdd(&d_cnt[dd], 1);
        atomicAdd(&d_loop[dd], ea[i]);
    }
}

__global__ void scanA_kernel() {
    __shared__ int sh[256];
    int b = blockIdx.x, t = threadIdx.x;
    int s = 0;
    for (int i = t; i < SCAN_CHUNK; i += 256) {
        int idx = b * SCAN_CHUNK + i;
        if (idx < NN) s += d_cnt[idx];
    }
    sh[t] = s; __syncthreads();
    for (int o = 128; o > 0; o >>= 1) {
        if (t < o) sh[t] += sh[t + o];
        __syncthreads();
    }
    if (t == 0) d_bsum[b] = sh[0];
}

__global__ void scanB_kernel() {
    __shared__ int sh[128];
    int t = threadIdx.x;
    int v = (t < SCAN_BLOCKS) ? d_bsum[t] : 0;
    sh[t] = v; __syncthreads();
    #pragma unroll
    for (int o = 1; o < 128; o <<= 1) {
        int x = (t >= o) ? sh[t - o] : 0;
        __syncthreads();
        sh[t] += x;
        __syncthreads();
    }
    if (t < SCAN_BLOCKS) d_bsum[t] = sh[t] - v;  // exclusive
}

__global__ void scanC_kernel() {
    __shared__ int sh[SCAN_CHUNK];
    int b = blockIdx.x, t = threadIdx.x;
    int idx = b * SCAN_CHUNK + t;
    int v = (idx < NN) ? d_cnt[idx] : 0;
    sh[t] = v; __syncthreads();
    for (int o = 1; o < SCAN_CHUNK; o <<= 1) {
        int x = (t >= o) ? sh[t - o] : 0;
        __syncthreads();
        sh[t] += x;
        __syncthreads();
    }
    int excl = sh[t] - v + d_bsum[b];
    if (idx < NN) { d_off[idx] = excl; d_cur[idx] = excl; }
    if (idx == NN - 1) d_off[NN] = excl + v;
}

__global__ void scatter_kernel(const int* __restrict__ ei, const float* __restrict__ ea) {
    int i = blockIdx.x * blockDim.x + threadIdx.x;
    if (i < EE) {
        int dd = ei[EE + i];
        int pos = atomicAdd(&d_cur[dd], 1);
        d_csr_src[pos] = ei[i];
        d_csr_ea[pos] = ea[i];
    }
}

// ---------------- linear: xph = half(x @ W^T), plus asrc/adst ---------------
#define LROWS 64
__global__ void __launch_bounds__(LROWS) lin_kernel(
    const float* __restrict__ x, const float* __restrict__ W,
    const float* __restrict__ a_src, const float* __restrict__ a_dst,
    __half2* __restrict__ xph, float* __restrict__ asrc, float* __restrict__ adst)
{
    __shared__ float Ws[FF * FF];
    __shared__ float As[FF], Ad[FF];
    __shared__ float Xs[LROWS][FF + 1];

    int tid = threadIdx.x;
    for (int i = tid; i < FF * FF; i += LROWS) Ws[i] = W[i];
    As[tid] = a_src[tid];
    Ad[tid] = a_dst[tid];

    int base = blockIdx.x * LROWS;
    for (int i = tid; i < LROWS * FF; i += LROWS) {
        int r = i / FF, c = i % FF;
        int node = base + r;
        Xs[r][c] = (node < NN) ? x[node * FF + c] : 0.f;
    }
    __syncthreads();

    float xr[FF];
    #pragma unroll
    for (int k = 0; k < FF; k++) xr[k] = Xs[tid][k];
    __syncthreads();

    int node = base + tid;
    float sa = 0.f, sd = 0.f;
    for (int j = 0; j < FF; j++) {
        float acc = 0.f;
        #pragma unroll
        for (int k = 0; k < FF; k++) acc += xr[k] * Ws[j * FF + k];
        Xs[tid][j] = acc;
        sa += acc * As[j];
        sd += acc * Ad[j];
    }
    if (node < NN) { asrc[node] = sa; adst[node] = sd; }
    __syncthreads();

    // write fp16 feature rows (coalesced 4B stores)
    for (int i = tid; i < LROWS * (FF / 2); i += LROWS) {
        int r = i / (FF / 2), c2 = i % (FF / 2);
        int nd = base + r;
        if (nd < NN)
            xph[nd * (FF / 2) + c2] = __floats2half2_rn(Xs[r][2 * c2], Xs[r][2 * c2 + 1]);
    }
}

// ---------------- aggregation: single-pass softmax, fp16 feature gather -----
__global__ void __launch_bounds__(256) agg_kernel(
    const __half2* __restrict__ xph, const float* __restrict__ asrc,
    const float* __restrict__ adst, const float* __restrict__ bias,
    float* __restrict__ hout, int cidx, int do_relu)
{
    int warp = (blockIdx.x * blockDim.x + threadIdx.x) >> 5;
    int lane = threadIdx.x & 31;
    if (warp >= NN) return;
    int d = warp;

    float ce = d_cedge[cidx];
    int start = d_off[d];
    int end   = d_off[d + 1];
    float adst_d = adst[d];
    int c = end - start;
    float loop_ea = d_loop[d] / fmaxf((float)c, 1.f);
    float wself = __expf(lrelu(asrc[d] + adst_d + loop_ea * ce));

    float2 xs = __half22float2(xph[d * 32 + lane]);
    float2 acc;
    acc.x = wself * xs.x;
    acc.y = wself * xs.y;
    float dsum = (lane == 0) ? wself : 0.f;

    for (int base = start; base < end; base += 32) {
        int j = base + lane;
        float w = 0.f;
        int s = 0;
        if (j < end) {
            s = d_csr_src[j];
            w = __expf(lrelu(asrc[s] + adst_d + d_csr_ea[j] * ce));
        }
        dsum += w;
        int nn = min(32, end - base);
        #pragma unroll 4
        for (int jj = 0; jj < nn; jj++) {
            float wj = __shfl_sync(0xffffffff, w, jj);
            int   sj = __shfl_sync(0xffffffff, s, jj);
            float2 xv = __half22float2(xph[sj * 32 + lane]);
            acc.x += wj * xv.x;
            acc.y += wj * xv.y;
        }
    }
    #pragma unroll
    for (int o = 16; o > 0; o >>= 1)
        dsum += __shfl_xor_sync(0xffffffff, dsum, o);

    float inv = 1.f / dsum;
    float2 out;
    out.x = acc.x * inv + bias[2 * lane];
    out.y = acc.y * inv + bias[2 * lane + 1];
    if (do_relu) {
        out.x = fmaxf(out.x, 0.f);
        out.y = fmaxf(out.y, 0.f);
    }
    ((float2*)hout)[d * 32 + lane] = out;
}

// ---------------- pool + FC + log_softmax -----------------------------------
__device__ __forceinline__ int lowerb(const int* a, int n, int key) {
    int lo = 0, hi = n;
    while (lo < hi) {
        int mid = (lo + hi) >> 1;
        if (a[mid] < key) lo = mid + 1; else hi = mid;
    }
    return lo;
}

__global__ void __launch_bounds__(64) pool_kernel(
    const int* __restrict__ batch, const float* __restrict__ h,
    const float* __restrict__ fcW, const float* __restrict__ fcb,
    float* __restrict__ out)
{
    int g = blockIdx.x;
    int t = threadIdx.x;
    __shared__ int s_lo, s_hi;
    if (t == 0) s_lo = lowerb(batch, NN, g);
    if (t == 1) s_hi = lowerb(batch, NN, g + 1);
    __syncthreads();
    int lo = s_lo, hi = s_hi;

    float sum = 0.f;
    #pragma unroll 4
    for (int i = lo; i < hi; i++) sum += h[i * FF + t];
    float pooled = sum / fmaxf((float)(hi - lo), 1.f);

    __shared__ float P[FF];
    __shared__ float logits[OUTD];
    P[t] = pooled;
    __syncthreads();
    if (t < OUTD) {
        float acc = fcb[t];
        #pragma unroll
        for (int k = 0; k < FF; k++) acc += P[k] * fcW[t * FF + k];
        logits[t] = acc;
    }
    __syncthreads();
    if (t == 0) {
        float mx = -CUDART_INF_F;
        #pragma unroll
        for (int o = 0; o < OUTD; o++) mx = fmaxf(mx, logits[o]);
        float se = 0.f;
        #pragma unroll
        for (int o = 0; o < OUTD; o++) se += __expf(logits[o] - mx);
        float lse = mx + __logf(se);
        #pragma unroll
        for (int o = 0; o < OUTD; o++) out[g * OUTD + o] = logits[o] - lse;
    }
}

// ---------------- launch ----------------------------------------------------
extern "C" void kernel_launch(void* const* d_in, const int* in_sizes, int n_in,
                              void* d_out, int out_size) {
    const float* x    = (const float*)d_in[0];
    const int*   ei   = (const int*)  d_in[1];
    const float* ea   = (const float*)d_in[2];
    const int*   batch= (const int*)  d_in[3];
    const float* W1   = (const float*)d_in[4];
    const float* as1  = (const float*)d_in[5];
    const float* ad1  = (const float*)d_in[6];
    const float* We1  = (const float*)d_in[7];
    const float* ae1  = (const float*)d_in[8];
    const float* b1   = (const float*)d_in[9];
    const float* W2   = (const float*)d_in[10];
    const float* as2  = (const float*)d_in[11];
    const float* ad2  = (const float*)d_in[12];
    const float* We2  = (const float*)d_in[13];
    const float* ae2  = (const float*)d_in[14];
    const float* b2   = (const float*)d_in[15];
    const float* fcW  = (const float*)d_in[16];
    const float* fcb  = (const float*)d_in[17];
    float* out = (float*)d_out;
    (void)in_sizes; (void)n_in; (void)out_size;

    // CSR build
    zero_kernel<<<(NN + 255) / 256, 256>>>(We1, ae1, We2, ae2);
    count_kernel<<<(EE + 255) / 256, 256>>>(ei, ea);
    scanA_kernel<<<SCAN_BLOCKS, 256>>>();
    scanB_kernel<<<1, 128>>>();
    scanC_kernel<<<SCAN_BLOCKS, SCAN_CHUNK>>>();
    scatter_kernel<<<(EE + 255) / 256, 256>>>(ei, ea);

    __half2* xph = nullptr; cudaGetSymbolAddress((void**)&xph, d_xph);
    float* h     = nullptr; cudaGetSymbolAddress((void**)&h,    d_h);
    float* asrc  = nullptr; cudaGetSymbolAddress((void**)&asrc, d_asrc);
    float* adst  = nullptr; cudaGetSymbolAddress((void**)&adst, d_adst);

    int agg_blocks = (NN * 32 + 255) / 256;

    // layer 1
    lin_kernel<<<(NN + LROWS - 1) / LROWS, LROWS>>>(x, W1, as1, ad1, xph, asrc, adst);
    agg_kernel<<<agg_blocks, 256>>>(xph, asrc, adst, b1, h, 0, 1);
    // layer 2
    lin_kernel<<<(NN + LROWS - 1) / LROWS, LROWS>>>(h, W2, as2, ad2, xph, asrc, adst);
    agg_kernel<<<agg_blocks, 256>>>(xph, asrc, adst, b2, h, 1, 0);
    // pool + fc + log_softmax
    pool_kernel<<<GG, FF>>>(batch, h, fcW, fcb, out);
}

// round 13
// speedup vs baseline: 1.1784x; 1.1784x over previous
#include <cuda_runtime.h>
#include <cuda_bf16.h>
#include <cuda_fp16.h>
#include <math_constants.h>
#include <mma.h>
using namespace nvcuda;

#define NN 100000
#define EE 800000
#define GG 512
#define FF 64
#define OUTD 10

#define SCAN_CHUNK 1024
#define SCAN_BLOCKS ((NN + SCAN_CHUNK - 1) / SCAN_CHUNK)

// ---------------- scratch (device globals; no allocation allowed) -----------
__device__ int     d_cnt[NN];
__device__ float   d_loop[NN];
__device__ int     d_off[NN + 1];
__device__ int     d_cur[NN];
__device__ int     d_bsum[SCAN_BLOCKS];
__device__ int     d_csr_src[EE];
__device__ float   d_csr_ea[EE];
__device__ __half2 d_xh[NN * (FF / 2)];    // fp16 copy of layer input (lin A operand)
__device__ __half2 d_xph[NN * (FF / 2)];   // fp16 projected features (gather path)
__device__ __half2 d_hh[NN * (FF / 2)];    // fp16 relu(layer-1 output) = lin2 input
__device__ float   d_h[NN * FF];           // fp32 layer-2 output (pool input)
__device__ float   d_asrc[NN];
__device__ float   d_adst[NN];
__device__ float   d_cedge[2];
__device__ __half  d_Wh1[FF * FF];
__device__ __half  d_Wh2[FF * FF];

__device__ __forceinline__ float lrelu(float x) {
    return fmaxf(x, 0.2f * x);
}

// ---------------- zero + cedge + W fp16 conversion (no barriers) -------------
__global__ void zero_kernel(const float* __restrict__ We1, const float* __restrict__ ae1,
                            const float* __restrict__ We2, const float* __restrict__ ae2,
                            const float* __restrict__ W1,  const float* __restrict__ W2) {
    int i = blockIdx.x * blockDim.x + threadIdx.x;
    if (i < NN) { d_cnt[i] = 0; d_loop[i] = 0.f; }
    if (blockIdx.x == 1) {
        for (int j = threadIdx.x; j < FF * FF; j += 256) d_Wh1[j] = __float2half(W1[j]);
    }
    if (blockIdx.x == 2) {
        for (int j = threadIdx.x; j < FF * FF; j += 256) d_Wh2[j] = __float2half(W2[j]);
    }
    if (blockIdx.x == 0 && threadIdx.x < 32) {
        int t = threadIdx.x;
        float p1 = We1[t] * ae1[t] + We1[t + 32] * ae1[t + 32];
        float p2 = We2[t] * ae2[t] + We2[t + 32] * ae2[t + 32];
        #pragma unroll
        for (int o = 16; o > 0; o >>= 1) {
            p1 += __shfl_xor_sync(0xffffffff, p1, o);
            p2 += __shfl_xor_sync(0xffffffff, p2, o);
        }
        if (t == 0) { d_cedge[0] = p1; d_cedge[1] = p2; }
    }
}

// convert x (fp32) -> d_xh (fp16)
__global__ void xhalf_kernel(const float* __restrict__ x) {
    int i = blockIdx.x * blockDim.x + threadIdx.x;
    if (i < NN * (FF / 2)) {
        float2 v = ((const float2*)x)[i];
        d_xh[i] = __floats2half2_rn(v.x, v.y);
    }
}

// ---------------- CSR construction ------------------------------------------
__global__ void count_kernel(const int* __restrict__ ei, const float* __restrict__ ea) {
    int i = blockIdx.x * blockDim.x + threadIdx.x;
    if (i < EE) {
        int dd = ei[EE + i];
        atomicAdd(&d_cnt[dd], 1);
        atomicAdd(&d_loop[dd], ea[i]);
    }
}

__global__ void scanA_kernel() {
    __shared__ int sh[256];
    int b = blockIdx.x, t = threadIdx.x;
    int s = 0;
    for (int i = t; i < SCAN_CHUNK; i += 256) {
        int idx = b * SCAN_CHUNK + i;
        if (idx < NN) s += d_cnt[idx];
    }
    sh[t] = s; __syncthreads();
    for (int o = 128; o > 0; o >>= 1) {
        if (t < o) sh[t] += sh[t + o];
        __syncthreads();
    }
    if (t == 0) d_bsum[b] = sh[0];
}

__global__ void scanB_kernel() {
    __shared__ int sh[128];
    int t = threadIdx.x;
    int v = (t < SCAN_BLOCKS) ? d_bsum[t] : 0;
    sh[t] = v; __syncthreads();
    #pragma unroll
    for (int o = 1; o < 128; o <<= 1) {
        int x = (t >= o) ? sh[t - o] : 0;
        __syncthreads();
        sh[t] += x;
        __syncthreads();
    }
    if (t < SCAN_BLOCKS) d_bsum[t] = sh[t] - v;  // exclusive
}

__global__ void scanC_kernel() {
    __shared__ int sh[SCAN_CHUNK];
    int b = blockIdx.x, t = threadIdx.x;
    int idx = b * SCAN_CHUNK + t;
    int v = (idx < NN) ? d_cnt[idx] : 0;
    sh[t] = v; __syncthreads();
    for (int o = 1; o < SCAN_CHUNK; o <<= 1) {
        int x = (t >= o) ? sh[t - o] : 0;
        __syncthreads();
        sh[t] += x;
        __syncthreads();
    }
    int excl = sh[t] - v + d_bsum[b];
    if (idx < NN) { d_off[idx] = excl; d_cur[idx] = excl; }
    if (idx == NN - 1) d_off[NN] = excl + v;
}

__global__ void scatter_kernel(const int* __restrict__ ei, const float* __restrict__ ea) {
    int i = blockIdx.x * blockDim.x + threadIdx.x;
    if (i < EE) {
        int dd = ei[EE + i];
        int pos = atomicAdd(&d_cur[dd], 1);
        d_csr_src[pos] = ei[i];
        d_csr_ea[pos] = ea[i];
    }
}

// ---------------- tensor-core linear: xp = A @ W^T --------------------------
// A: fp16 [NN,64] (d_xh or d_hh). W: fp16 [64,64] row-major W[j][k].
// C[i][j] = sum_k A[i][k] * W[j][k]  -> wmma A row_major, B col_major on W.
// Block: 128 threads = 4 warps, 64 rows. fp32 accumulate in smem, then:
// asrc/adst row-dots (fp32) + fp16 xph write.
__global__ void __launch_bounds__(128) lin_tc_kernel(
    const __half2* __restrict__ xh, const __half* __restrict__ Wh,
    const float* __restrict__ a_src, const float* __restrict__ a_dst,
    __half2* __restrict__ xph, float* __restrict__ asrc, float* __restrict__ adst)
{
    __shared__ __half sA[64 * 72];
    __shared__ __half sB[64 * 72];
    __shared__ float  sC[64 * 68];

    int tid = threadIdx.x;
    int wid = tid >> 5;
    int base = blockIdx.x * 64;

    // stage A (64x64 fp16, row stride 72) and B (= W, row stride 72)
    for (int i = tid; i < 64 * 32; i += 128) {
        int r = i >> 5, c2 = i & 31;
        int node = base + r;
        __half2 v = (node < NN) ? xh[node * 32 + c2] : __floats2half2_rn(0.f, 0.f);
        *reinterpret_cast<__half2*>(&sA[r * 72 + c2 * 2]) = v;
        *reinterpret_cast<__half2*>(&sB[r * 72 + c2 * 2]) =
            *reinterpret_cast<const __half2*>(&Wh[r * 64 + c2 * 2]);
    }
    __syncthreads();

    wmma::fragment<wmma::accumulator, 16, 16, 16, float> c[4];
    #pragma unroll
    for (int n = 0; n < 4; n++) wmma::fill_fragment(c[n], 0.f);
    #pragma unroll
    for (int k = 0; k < 4; k++) {
        wmma::fragment<wmma::matrix_a, 16, 16, 16, __half, wmma::row_major> a;
        wmma::load_matrix_sync(a, sA + wid * 16 * 72 + k * 16, 72);
        #pragma unroll
        for (int n = 0; n < 4; n++) {
            wmma::fragment<wmma::matrix_b, 16, 16, 16, __half, wmma::col_major> b;
            wmma::load_matrix_sync(b, sB + (n * 16) * 72 + k * 16, 72);
            wmma::mma_sync(c[n], a, b, c[n]);
        }
    }
    #pragma unroll
    for (int n = 0; n < 4; n++)
        wmma::store_matrix_sync(sC + wid * 16 * 68 + n * 16, c[n], 68, wmma::mem_row_major);
    __syncthreads();

    // asrc/adst: one thread per row (fp32, from fp32 accumulators)
    if (tid < 64) {
        int node = base + tid;
        if (node < NN) {
            float sa = 0.f, sd = 0.f;
            #pragma unroll
            for (int j = 0; j < FF; j++) {
                float v = sC[tid * 68 + j];
                sa += v * a_src[j];
                sd += v * a_dst[j];
            }
            asrc[node] = sa; adst[node] = sd;
        }
    }
    // xph: fp16 feature rows, coalesced
    for (int i = tid; i < 64 * 32; i += 128) {
        int r = i >> 5, c2 = i & 31;
        int node = base + r;
        if (node < NN)
            xph[node * 32 + c2] = __floats2half2_rn(sC[r * 68 + 2 * c2], sC[r * 68 + 2 * c2 + 1]);
    }
}

// ---------------- aggregation: single-pass softmax, fp16 feature gather -----
// layer==0: write relu(out) as fp16 to hh (lin2 input). layer==1: fp32 to hout.
__global__ void __launch_bounds__(256) agg_kernel(
    const __half2* __restrict__ xph, const float* __restrict__ asrc,
    const float* __restrict__ adst, const float* __restrict__ bias,
    float* __restrict__ hout, __half2* __restrict__ hh, int layer)
{
    int warp = (blockIdx.x * blockDim.x + threadIdx.x) >> 5;
    int lane = threadIdx.x & 31;
    if (warp >= NN) return;
    int d = warp;

    float ce = d_cedge[layer];
    int start = d_off[d];
    int end   = d_off[d + 1];
    float adst_d = adst[d];
    int c = end - start;
    float loop_ea = d_loop[d] / fmaxf((float)c, 1.f);
    float wself = __expf(lrelu(asrc[d] + adst_d + loop_ea * ce));

    float2 xs = __half22float2(xph[d * 32 + lane]);
    float2 acc;
    acc.x = wself * xs.x;
    acc.y = wself * xs.y;
    float dsum = (lane == 0) ? wself : 0.f;

    for (int base = start; base < end; base += 32) {
        int j = base + lane;
        float w = 0.f;
        int s = 0;
        if (j < end) {
            s = d_csr_src[j];
            w = __expf(lrelu(asrc[s] + adst_d + d_csr_ea[j] * ce));
        }
        dsum += w;
        int nn = min(32, end - base);
        #pragma unroll 4
        for (int jj = 0; jj < nn; jj++) {
            float wj = __shfl_sync(0xffffffff, w, jj);
            int   sj = __shfl_sync(0xffffffff, s, jj);
            float2 xv = __half22float2(xph[sj * 32 + lane]);
            acc.x += wj * xv.x;
            acc.y += wj * xv.y;
        }
    }
    #pragma unroll
    for (int o = 16; o > 0; o >>= 1)
        dsum += __shfl_xor_sync(0xffffffff, dsum, o);

    float inv = 1.f / dsum;
    float ox = acc.x * inv + bias[2 * lane];
    float oy = acc.y * inv + bias[2 * lane + 1];
    if (layer == 0) {
        ox = fmaxf(ox, 0.f);
        oy = fmaxf(oy, 0.f);
        hh[d * 32 + lane] = __floats2half2_rn(ox, oy);
    } else {
        ((float2*)hout)[d * 32 + lane] = make_float2(ox, oy);
    }
}

// ---------------- pool + FC + log_softmax -----------------------------------
__device__ __forceinline__ int lowerb(const int* a, int n, int key) {
    int lo = 0, hi = n;
    while (lo < hi) {
        int mid = (lo + hi) >> 1;
        if (a[mid] < key) lo = mid + 1; else hi = mid;
    }
    return lo;
}

__global__ void __launch_bounds__(64) pool_kernel(
    const int* __restrict__ batch, const float* __restrict__ h,
    const float* __restrict__ fcW, const float* __restrict__ fcb,
    float* __restrict__ out)
{
    int g = blockIdx.x;
    int t = threadIdx.x;
    __shared__ int s_lo, s_hi;
    if (t == 0) s_lo = lowerb(batch, NN, g);
    if (t == 1) s_hi = lowerb(batch, NN, g + 1);
    __syncthreads();
    int lo = s_lo, hi = s_hi;

    float sum = 0.f;
    #pragma unroll 4
    for (int i = lo; i < hi; i++) sum += h[i * FF + t];
    float pooled = sum / fmaxf((float)(hi - lo), 1.f);

    __shared__ float P[FF];
    __shared__ float logits[OUTD];
    P[t] = pooled;
    __syncthreads();
    if (t < OUTD) {
        float acc = fcb[t];
        #pragma unroll
        for (int k = 0; k < FF; k++) acc += P[k] * fcW[t * FF + k];
        logits[t] = acc;
    }
    __syncthreads();
    if (t == 0) {
        float mx = -CUDART_INF_F;
        #pragma unroll
        for (int o = 0; o < OUTD; o++) mx = fmaxf(mx, logits[o]);
        float se = 0.f;
        #pragma unroll
        for (int o = 0; o < OUTD; o++) se += __expf(logits[o] - mx);
        float lse = mx + __logf(se);
        #pragma unroll
        for (int o = 0; o < OUTD; o++) out[g * OUTD + o] = logits[o] - lse;
    }
}

// ---------------- launch ----------------------------------------------------
extern "C" void kernel_launch(void* const* d_in, const int* in_sizes, int n_in,
                              void* d_out, int out_size) {
    const float* x    = (const float*)d_in[0];
    const int*   ei   = (const int*)  d_in[1];
    const float* ea   = (const float*)d_in[2];
    const int*   batch= (const int*)  d_in[3];
    const float* W1   = (const float*)d_in[4];
    const float* as1  = (const float*)d_in[5];
    const float* ad1  = (const float*)d_in[6];
    const float* We1  = (const float*)d_in[7];
    const float* ae1  = (const float*)d_in[8];
    const float* b1   = (const float*)d_in[9];
    const float* W2   = (const float*)d_in[10];
    const float* as2  = (const float*)d_in[11];
    const float* ad2  = (const float*)d_in[12];
    const float* We2  = (const float*)d_in[13];
    const float* ae2  = (const float*)d_in[14];
    const float* b2   = (const float*)d_in[15];
    const float* fcW  = (const float*)d_in[16];
    const float* fcb  = (const float*)d_in[17];
    float* out = (float*)d_out;
    (void)in_sizes; (void)n_in; (void)out_size;

    __half2* xh  = nullptr; cudaGetSymbolAddress((void**)&xh,  d_xh);
    __half2* xph = nullptr; cudaGetSymbolAddress((void**)&xph, d_xph);
    __half2* hh  = nullptr; cudaGetSymbolAddress((void**)&hh,  d_hh);
    float* h     = nullptr; cudaGetSymbolAddress((void**)&h,    d_h);
    float* asrc  = nullptr; cudaGetSymbolAddress((void**)&asrc, d_asrc);
    float* adst  = nullptr; cudaGetSymbolAddress((void**)&adst, d_adst);
    __half* Wh1  = nullptr; cudaGetSymbolAddress((void**)&Wh1, d_Wh1);
    __half* Wh2  = nullptr; cudaGetSymbolAddress((void**)&Wh2, d_Wh2);

    // CSR build + conversions
    zero_kernel<<<(NN + 255) / 256, 256>>>(We1, ae1, We2, ae2, W1, W2);
    xhalf_kernel<<<(NN * (FF / 2) + 255) / 256, 256>>>(x);
    count_kernel<<<(EE + 255) / 256, 256>>>(ei, ea);
    scanA_kernel<<<SCAN_BLOCKS, 256>>>();
    scanB_kernel<<<1, 128>>>();
    scanC_kernel<<<SCAN_BLOCKS, SCAN_CHUNK>>>();
    scatter_kernel<<<(EE + 255) / 256, 256>>>(ei, ea);

    int agg_blocks = (NN * 32 + 255) / 256;
    int lin_blocks = (NN + 63) / 64;

    // layer 1
    lin_tc_kernel<<<lin_blocks, 128>>>(xh, Wh1, as1, ad1, xph, asrc, adst);
    agg_kernel<<<agg_blocks, 256>>>(xph, asrc, adst, b1, h, hh, 0);
    // layer 2
    lin_tc_kernel<<<lin_blocks, 128>>>(hh, Wh2, as2, ad2, xph, asrc, adst);
    agg_kernel<<<agg_blocks, 256>>>(xph, asrc, adst, b2, h, hh, 1);
    // pool + fc + log_softmax
    pool_kernel<<<GG, FF>>>(batch, h, fcW, fcb, out);
}

// round 14
// speedup vs baseline: 1.2380x; 1.0506x over previous
#include <cuda_runtime.h>
#include <cuda_bf16.h>
#include <cuda_fp16.h>
#include <math_constants.h>
#include <mma.h>
using namespace nvcuda;

#define NN 100000
#define EE 800000
#define GG 512
#define FF 64
#define OUTD 10

#define SCAN_CHUNK 1024
#define SCAN_BLOCKS ((NN + SCAN_CHUNK - 1) / SCAN_CHUNK)

// ---------------- scratch (device globals; no allocation allowed) -----------
__device__ int     d_cnt[NN];
__device__ float   d_loop[NN];
__device__ int     d_off[NN + 1];
__device__ int     d_cur[NN];
__device__ int     d_bsum[SCAN_BLOCKS];
__device__ int     d_csr_src[EE];
__device__ float   d_csr_ea[EE];
__device__ __half2 d_xh[NN * (FF / 2)];    // fp16 copy of layer input (lin A operand)
__device__ __half2 d_xph[NN * (FF / 2)];   // fp16 projected features (gather path)
__device__ __half2 d_hh[NN * (FF / 2)];    // fp16 relu(layer-1 output) = lin2 input
__device__ float   d_h[NN * FF];           // fp32 layer-2 output (pool input)
__device__ float   d_asrc[NN];
__device__ float   d_adst[NN];
__device__ float   d_cedge[2];
__device__ __half  d_Wh1[FF * FF];
__device__ __half  d_Wh2[FF * FF];

__device__ __forceinline__ float lrelu(float x) {
    return fmaxf(x, 0.2f * x);
}

// ---------------- zero + xhalf + cedge + W fp16 conversion (no barriers) ----
// grid covers NN*FF/2 elements (the xh conversion range)
__global__ void zero_kernel(const float* __restrict__ x,
                            const float* __restrict__ We1, const float* __restrict__ ae1,
                            const float* __restrict__ We2, const float* __restrict__ ae2,
                            const float* __restrict__ W1,  const float* __restrict__ W2) {
    int i = blockIdx.x * blockDim.x + threadIdx.x;
    if (i < NN) { d_cnt[i] = 0; d_loop[i] = 0.f; }
    if (i < NN * (FF / 2)) {
        float2 v = ((const float2*)x)[i];
        d_xh[i] = __floats2half2_rn(v.x, v.y);
    }
    if (blockIdx.x == 1) {
        for (int j = threadIdx.x; j < FF * FF; j += 256) d_Wh1[j] = __float2half(W1[j]);
    }
    if (blockIdx.x == 2) {
        for (int j = threadIdx.x; j < FF * FF; j += 256) d_Wh2[j] = __float2half(W2[j]);
    }
    if (blockIdx.x == 0 && threadIdx.x < 32) {
        int t = threadIdx.x;
        float p1 = We1[t] * ae1[t] + We1[t + 32] * ae1[t + 32];
        float p2 = We2[t] * ae2[t] + We2[t + 32] * ae2[t + 32];
        #pragma unroll
        for (int o = 16; o > 0; o >>= 1) {
            p1 += __shfl_xor_sync(0xffffffff, p1, o);
            p2 += __shfl_xor_sync(0xffffffff, p2, o);
        }
        if (t == 0) { d_cedge[0] = p1; d_cedge[1] = p2; }
    }
}

// ---------------- CSR construction ------------------------------------------
__global__ void count_kernel(const int* __restrict__ ei, const float* __restrict__ ea) {
    int i = blockIdx.x * blockDim.x + threadIdx.x;
    if (i < EE) {
        int dd = ei[EE + i];
        atomicAdd(&d_cnt[dd], 1);
        atomicAdd(&d_loop[dd], ea[i]);
    }
}

__global__ void scanA_kernel() {
    __shared__ int sh[256];
    int b = blockIdx.x, t = threadIdx.x;
    int s = 0;
    for (int i = t; i < SCAN_CHUNK; i += 256) {
        int idx = b * SCAN_CHUNK + i;
        if (idx < NN) s += d_cnt[idx];
    }
    sh[t] = s; __syncthreads();
    for (int o = 128; o > 0; o >>= 1) {
        if (t < o) sh[t] += sh[t + o];
        __syncthreads();
    }
    if (t == 0) d_bsum[b] = sh[0];
}

// scanC with scanB merged: each block does a parallel 128-wide scan of the
// 98 chunk sums in smem (all threads participate in barriers — no divergence)
__global__ void __launch_bounds__(SCAN_CHUNK) scanC_kernel() {
    __shared__ int sh[SCAN_CHUNK];
    __shared__ int sb[128];
    int b = blockIdx.x, t = threadIdx.x;

    // parallel inclusive scan of chunk sums (first 128 threads hold data)
    if (t < 128) sb[t] = (t < SCAN_BLOCKS) ? d_bsum[t] : 0;
    __syncthreads();
    #pragma unroll
    for (int o = 1; o < 128; o <<= 1) {
        int x = (t < 128 && t >= o) ? sb[t - o] : 0;
        __syncthreads();
        if (t < 128) sb[t] += x;
        __syncthreads();
    }
    int base = (b > 0) ? sb[b - 1] : 0;

    int idx = b * SCAN_CHUNK + t;
    int v = (idx < NN) ? d_cnt[idx] : 0;
    sh[t] = v; __syncthreads();
    for (int o = 1; o < SCAN_CHUNK; o <<= 1) {
        int x = (t >= o) ? sh[t - o] : 0;
        __syncthreads();
        sh[t] += x;
        __syncthreads();
    }
    int excl = sh[t] - v + base;
    if (idx < NN) { d_off[idx] = excl; d_cur[idx] = excl; }
    if (idx == NN - 1) d_off[NN] = excl + v;
}

__global__ void scatter_kernel(const int* __restrict__ ei, const float* __restrict__ ea) {
    int i = blockIdx.x * blockDim.x + threadIdx.x;
    if (i < EE) {
        int dd = ei[EE + i];
        int pos = atomicAdd(&d_cur[dd], 1);
        d_csr_src[pos] = ei[i];
        d_csr_ea[pos] = ea[i];
    }
}

// ---------------- tensor-core linear: xp = A @ W^T --------------------------
__global__ void __launch_bounds__(128) lin_tc_kernel(
    const __half2* __restrict__ xh, const __half* __restrict__ Wh,
    const float* __restrict__ a_src, const float* __restrict__ a_dst,
    __half2* __restrict__ xph, float* __restrict__ asrc, float* __restrict__ adst)
{
    __shared__ __half sA[64 * 72];
    __shared__ __half sB[64 * 72];
    __shared__ float  sC[64 * 68];

    int tid = threadIdx.x;
    int wid = tid >> 5;
    int base = blockIdx.x * 64;

    for (int i = tid; i < 64 * 32; i += 128) {
        int r = i >> 5, c2 = i & 31;
        int node = base + r;
        __half2 v = (node < NN) ? xh[node * 32 + c2] : __floats2half2_rn(0.f, 0.f);
        *reinterpret_cast<__half2*>(&sA[r * 72 + c2 * 2]) = v;
        *reinterpret_cast<__half2*>(&sB[r * 72 + c2 * 2]) =
            *reinterpret_cast<const __half2*>(&Wh[r * 64 + c2 * 2]);
    }
    __syncthreads();

    wmma::fragment<wmma::accumulator, 16, 16, 16, float> c[4];
    #pragma unroll
    for (int n = 0; n < 4; n++) wmma::fill_fragment(c[n], 0.f);
    #pragma unroll
    for (int k = 0; k < 4; k++) {
        wmma::fragment<wmma::matrix_a, 16, 16, 16, __half, wmma::row_major> a;
        wmma::load_matrix_sync(a, sA + wid * 16 * 72 + k * 16, 72);
        #pragma unroll
        for (int n = 0; n < 4; n++) {
            wmma::fragment<wmma::matrix_b, 16, 16, 16, __half, wmma::col_major> b;
            wmma::load_matrix_sync(b, sB + (n * 16) * 72 + k * 16, 72);
            wmma::mma_sync(c[n], a, b, c[n]);
        }
    }
    #pragma unroll
    for (int n = 0; n < 4; n++)
        wmma::store_matrix_sync(sC + wid * 16 * 68 + n * 16, c[n], 68, wmma::mem_row_major);
    __syncthreads();

    if (tid < 64) {
        int node = base + tid;
        if (node < NN) {
            float sa = 0.f, sd = 0.f;
            #pragma unroll
            for (int j = 0; j < FF; j++) {
                float v = sC[tid * 68 + j];
                sa += v * a_src[j];
                sd += v * a_dst[j];
            }
            asrc[node] = sa; adst[node] = sd;
        }
    }
    for (int i = tid; i < 64 * 32; i += 128) {
        int r = i >> 5, c2 = i & 31;
        int node = base + r;
        if (node < NN)
            xph[node * 32 + c2] = __floats2half2_rn(sC[r * 68 + 2 * c2], sC[r * 68 + 2 * c2 + 1]);
    }
}

// ---------------- aggregation: single-pass softmax, fp16 feature gather -----
__global__ void __launch_bounds__(256) agg_kernel(
    const __half2* __restrict__ xph, const float* __restrict__ asrc,
    const float* __restrict__ adst, const float* __restrict__ bias,
    float* __restrict__ hout, __half2* __restrict__ hh, int layer)
{
    int warp = (blockIdx.x * blockDim.x + threadIdx.x) >> 5;
    int lane = threadIdx.x & 31;
    if (warp >= NN) return;
    int d = warp;

    float ce = d_cedge[layer];
    int start = d_off[d];
    int end   = d_off[d + 1];
    float adst_d = adst[d];
    int c = end - start;
    float loop_ea = d_loop[d] / fmaxf((float)c, 1.f);
    float wself = __expf(lrelu(asrc[d] + adst_d + loop_ea * ce));

    float2 xs = __half22float2(xph[d * 32 + lane]);
    float2 acc;
    acc.x = wself * xs.x;
    acc.y = wself * xs.y;
    float dsum = (lane == 0) ? wself : 0.f;

    for (int base = start; base < end; base += 32) {
        int j = base + lane;
        float w = 0.f;
        int s = 0;
        if (j < end) {
            s = d_csr_src[j];
            w = __expf(lrelu(asrc[s] + adst_d + d_csr_ea[j] * ce));
        }
        dsum += w;
        int nn = min(32, end - base);
        #pragma unroll 4
        for (int jj = 0; jj < nn; jj++) {
            float wj = __shfl_sync(0xffffffff, w, jj);
            int   sj = __shfl_sync(0xffffffff, s, jj);
            float2 xv = __half22float2(xph[sj * 32 + lane]);
            acc.x += wj * xv.x;
            acc.y += wj * xv.y;
        }
    }
    #pragma unroll
    for (int o = 16; o > 0; o >>= 1)
        dsum += __shfl_xor_sync(0xffffffff, dsum, o);

    float inv = 1.f / dsum;
    float ox = acc.x * inv + bias[2 * lane];
    float oy = acc.y * inv + bias[2 * lane + 1];
    if (layer == 0) {
        ox = fmaxf(ox, 0.f);
        oy = fmaxf(oy, 0.f);
        hh[d * 32 + lane] = __floats2half2_rn(ox, oy);
    } else {
        ((float2*)hout)[d * 32 + lane] = make_float2(ox, oy);
    }
}

// ---------------- pool + FC + log_softmax -----------------------------------
__device__ __forceinline__ int lowerb(const int* a, int n, int key) {
    int lo = 0, hi = n;
    while (lo < hi) {
        int mid = (lo + hi) >> 1;
        if (a[mid] < key) lo = mid + 1; else hi = mid;
    }
    return lo;
}

__global__ void __launch_bounds__(64) pool_kernel(
    const int* __restrict__ batch, const float* __restrict__ h,
    const float* __restrict__ fcW, const float* __restrict__ fcb,
    float* __restrict__ out)
{
    int g = blockIdx.x;
    int t = threadIdx.x;
    __shared__ int s_lo, s_hi;
    if (t == 0) s_lo = lowerb(batch, NN, g);
    if (t == 1) s_hi = lowerb(batch, NN, g + 1);
    __syncthreads();
    int lo = s_lo, hi = s_hi;

    float sum = 0.f;
    #pragma unroll 4
    for (int i = lo; i < hi; i++) sum += h[i * FF + t];
    float pooled = sum / fmaxf((float)(hi - lo), 1.f);

    __shared__ float P[FF];
    __shared__ float logits[OUTD];
    P[t] = pooled;
    __syncthreads();
    if (t < OUTD) {
        float acc = fcb[t];
        #pragma unroll
        for (int k = 0; k < FF; k++) acc += P[k] * fcW[t * FF + k];
        logits[t] = acc;
    }
    __syncthreads();
    if (t == 0) {
        float mx = -CUDART_INF_F;
        #pragma unroll
        for (int o = 0; o < OUTD; o++) mx = fmaxf(mx, logits[o]);
        float se = 0.f;
        #pragma unroll
        for (int o = 0; o < OUTD; o++) se += __expf(logits[o] - mx);
        float lse = mx + __logf(se);
        #pragma unroll
        for (int o = 0; o < OUTD; o++) out[g * OUTD + o] = logits[o] - lse;
    }
}

// ---------------- launch ----------------------------------------------------
extern "C" void kernel_launch(void* const* d_in, const int* in_sizes, int n_in,
                              void* d_out, int out_size) {
    const float* x    = (const float*)d_in[0];
    const int*   ei   = (const int*)  d_in[1];
    const float* ea   = (const float*)d_in[2];
    const int*   batch= (const int*)  d_in[3];
    const float* W1   = (const float*)d_in[4];
    const float* as1  = (const float*)d_in[5];
    const float* ad1  = (const float*)d_in[6];
    const float* We1  = (const float*)d_in[7];
    const float* ae1  = (const float*)d_in[8];
    const float* b1   = (const float*)d_in[9];
    const float* W2   = (const float*)d_in[10];
    const float* as2  = (const float*)d_in[11];
    const float* ad2  = (const float*)d_in[12];
    const float* We2  = (const float*)d_in[13];
    const float* ae2  = (const float*)d_in[14];
    const float* b2   = (const float*)d_in[15];
    const float* fcW  = (const float*)d_in[16];
    const float* fcb  = (const float*)d_in[17];
    float* out = (float*)d_out;
    (void)in_sizes; (void)n_in; (void)out_size;

    __half2* xh  = nullptr; cudaGetSymbolAddress((void**)&xh,  d_xh);
    __half2* xph = nullptr; cudaGetSymbolAddress((void**)&xph, d_xph);
    __half2* hh  = nullptr; cudaGetSymbolAddress((void**)&hh,  d_hh);
    float* h     = nullptr; cudaGetSymbolAddress((void**)&h,    d_h);
    float* asrc  = nullptr; cudaGetSymbolAddress((void**)&asrc, d_asrc);
    float* adst  = nullptr; cudaGetSymbolAddress((void**)&adst, d_adst);
    __half* Wh1  = nullptr; cudaGetSymbolAddress((void**)&Wh1, d_Wh1);
    __half* Wh2  = nullptr; cudaGetSymbolAddress((void**)&Wh2, d_Wh2);

    // CSR build + conversions (xhalf fused into zero; scanB fused into scanC)
    zero_kernel<<<(NN * (FF / 2) + 255) / 256, 256>>>(x, We1, ae1, We2, ae2, W1, W2);
    count_kernel<<<(EE + 255) / 256, 256>>>(ei, ea);
    scanA_kernel<<<SCAN_BLOCKS, 256>>>();
    scanC_kernel<<<SCAN_BLOCKS, SCAN_CHUNK>>>();
    scatter_kernel<<<(EE + 255) / 256, 256>>>(ei, ea);

    int agg_blocks = (NN * 32 + 255) / 256;
    int lin_blocks = (NN + 63) / 64;

    // layer 1
    lin_tc_kernel<<<lin_blocks, 128>>>(xh, Wh1, as1, ad1, xph, asrc, adst);
    agg_kernel<<<agg_blocks, 256>>>(xph, asrc, adst, b1, h, hh, 0);
    // layer 2
    lin_tc_kernel<<<lin_blocks, 128>>>(hh, Wh2, as2, ad2, xph, asrc, adst);
    agg_kernel<<<agg_blocks, 256>>>(xph, asrc, adst, b2, h, hh, 1);
    // pool + fc + log_softmax
    pool_kernel<<<GG, FF>>>(batch, h, fcW, fcb, out);
}

// round 16
// speedup vs baseline: 1.2528x; 1.0120x over previous
#include <cuda_runtime.h>
#include <cuda_bf16.h>
#include <cuda_fp16.h>
#include <math_constants.h>
#include <mma.h>
using namespace nvcuda;

#define NN 100000
#define EE 800000
#define GG 512
#define FF 64
#define OUTD 10

#define SCAN_CHUNK 1024
#define SCAN_BLOCKS ((NN + SCAN_CHUNK - 1) / SCAN_CHUNK)
#define LIN_BLOCKS ((NN + 63) / 64)
#define CNT_BLOCKS ((EE + 255) / 256)

// ---------------- scratch (device globals; no allocation allowed) -----------
__device__ int     d_cnt[NN];
__device__ int     d_off[NN + 1];
__device__ int     d_cur[NN];
__device__ int     d_bsum[SCAN_BLOCKS];
__device__ int     d_csr_src[EE];
__device__ float   d_csr_ea[EE];
__device__ __half2 d_xh[NN * (FF / 2)];    // fp16 layer input (lin A operand)
__device__ __half2 d_xph[NN * (FF / 2)];   // fp16 projected features (gather path)
__device__ __half2 d_hh[NN * (FF / 2)];    // fp16 relu(layer-1 out) = lin2 input
__device__ float   d_h[NN * FF];           // fp32 layer-2 output (pool input)
__device__ float   d_asrc[NN];
__device__ float   d_adst[NN];
__device__ float   d_cedge[2];
__device__ __half  d_Wh1[FF * FF];
__device__ __half  d_Wh2[FF * FF];

__device__ __forceinline__ float lrelu(float x) {
    return fmaxf(x, 0.2f * x);
}

// ---------------- zero + xhalf + cedge + W fp16 conversion (no barriers) ----
__global__ void zero_kernel(const float* __restrict__ x,
                            const float* __restrict__ We1, const float* __restrict__ ae1,
                            const float* __restrict__ We2, const float* __restrict__ ae2,
                            const float* __restrict__ W1,  const float* __restrict__ W2) {
    int i = blockIdx.x * blockDim.x + threadIdx.x;
    if (i < NN) d_cnt[i] = 0;
    if (i < NN * (FF / 2)) {
        float2 v = ((const float2*)x)[i];
        d_xh[i] = __floats2half2_rn(v.x, v.y);
    }
    if (blockIdx.x == 1) {
        for (int j = threadIdx.x; j < FF * FF; j += 256) d_Wh1[j] = __float2half(W1[j]);
    }
    if (blockIdx.x == 2) {
        for (int j = threadIdx.x; j < FF * FF; j += 256) d_Wh2[j] = __float2half(W2[j]);
    }
    if (blockIdx.x == 0 && threadIdx.x < 32) {
        int t = threadIdx.x;
        float p1 = We1[t] * ae1[t] + We1[t + 32] * ae1[t + 32];
        float p2 = We2[t] * ae2[t] + We2[t + 32] * ae2[t + 32];
        #pragma unroll
        for (int o = 16; o > 0; o >>= 1) {
            p1 += __shfl_xor_sync(0xffffffff, p1, o);
            p2 += __shfl_xor_sync(0xffffffff, p2, o);
        }
        if (t == 0) { d_cedge[0] = p1; d_cedge[1] = p2; }
    }
}

// ---------------- tensor-core linear body (256-thread blocks, 64 rows) ------
__device__ __forceinline__ void lin_body(
    int base,
    const __half2* __restrict__ xh, const __half* __restrict__ Wh,
    const float* __restrict__ a_src, const float* __restrict__ a_dst,
    __half2* __restrict__ xph, float* __restrict__ asrc, float* __restrict__ adst)
{
    __shared__ __half sA[64 * 72];
    __shared__ __half sB[64 * 72];
    __shared__ float  sC[64 * 68];

    int tid = threadIdx.x;
    int wid = tid >> 5;

    for (int i = tid; i < 64 * 32; i += 256) {
        int r = i >> 5, c2 = i & 31;
        int node = base + r;
        __half2 v = (node < NN) ? xh[node * 32 + c2] : __floats2half2_rn(0.f, 0.f);
        *reinterpret_cast<__half2*>(&sA[r * 72 + c2 * 2]) = v;
        *reinterpret_cast<__half2*>(&sB[r * 72 + c2 * 2]) =
            *reinterpret_cast<const __half2*>(&Wh[r * 64 + c2 * 2]);
    }
    __syncthreads();

    if (wid < 4) {
        wmma::fragment<wmma::accumulator, 16, 16, 16, float> c[4];
        #pragma unroll
        for (int n = 0; n < 4; n++) wmma::fill_fragment(c[n], 0.f);
        #pragma unroll
        for (int k = 0; k < 4; k++) {
            wmma::fragment<wmma::matrix_a, 16, 16, 16, __half, wmma::row_major> a;
            wmma::load_matrix_sync(a, sA + wid * 16 * 72 + k * 16, 72);
            #pragma unroll
            for (int n = 0; n < 4; n++) {
                wmma::fragment<wmma::matrix_b, 16, 16, 16, __half, wmma::col_major> b;
                wmma::load_matrix_sync(b, sB + (n * 16) * 72 + k * 16, 72);
                wmma::mma_sync(c[n], a, b, c[n]);
            }
        }
        #pragma unroll
        for (int n = 0; n < 4; n++)
            wmma::store_matrix_sync(sC + wid * 16 * 68 + n * 16, c[n], 68, wmma::mem_row_major);
    }
    __syncthreads();

    if (tid < 64) {
        int node = base + tid;
        if (node < NN) {
            float sa = 0.f, sd = 0.f;
            #pragma unroll
            for (int j = 0; j < FF; j++) {
                float v = sC[tid * 68 + j];
                sa += v * a_src[j];
                sd += v * a_dst[j];
            }
            asrc[node] = sa; adst[node] = sd;
        }
    }
    for (int i = tid; i < 64 * 32; i += 256) {
        int r = i >> 5, c2 = i & 31;
        int node = base + r;
        if (node < NN)
            xph[node * 32 + c2] = __floats2half2_rn(sC[r * 68 + 2 * c2], sC[r * 68 + 2 * c2 + 1]);
    }
}

// ---------------- fused: lin1 (blocks [0,LIN_BLOCKS)) + count (rest) --------
// branch is uniform per block: every thread of a block takes the same path,
// so lin_body's __syncthreads are non-divergent.
__global__ void __launch_bounds__(256) count_lin_kernel(
    const int* __restrict__ ei,
    const __half2* __restrict__ xh, const __half* __restrict__ Wh,
    const float* __restrict__ a_src, const float* __restrict__ a_dst,
    __half2* __restrict__ xph, float* __restrict__ asrc, float* __restrict__ adst)
{
    if (blockIdx.x < LIN_BLOCKS) {
        lin_body(blockIdx.x * 64, xh, Wh, a_src, a_dst, xph, asrc, adst);
    } else {
        int i = (blockIdx.x - LIN_BLOCKS) * 256 + threadIdx.x;
        if (i < EE) atomicAdd(&d_cnt[ei[EE + i]], 1);
    }
}

// standalone lin for layer 2
__global__ void __launch_bounds__(256) lin_tc_kernel(
    const __half2* __restrict__ xh, const __half* __restrict__ Wh,
    const float* __restrict__ a_src, const float* __restrict__ a_dst,
    __half2* __restrict__ xph, float* __restrict__ asrc, float* __restrict__ adst)
{
    lin_body(blockIdx.x * 64, xh, Wh, a_src, a_dst, xph, asrc, adst);
}

// ---------------- scan ------------------------------------------------------
__global__ void scanA_kernel() {
    __shared__ int sh[256];
    int b = blockIdx.x, t = threadIdx.x;
    int s = 0;
    for (int i = t; i < SCAN_CHUNK; i += 256) {
        int idx = b * SCAN_CHUNK + i;
        if (idx < NN) s += d_cnt[idx];
    }
    sh[t] = s; __syncthreads();
    for (int o = 128; o > 0; o >>= 1) {
        if (t < o) sh[t] += sh[t + o];
        __syncthreads();
    }
    if (t == 0) d_bsum[b] = sh[0];
}

__global__ void __launch_bounds__(SCAN_CHUNK) scanC_kernel() {
    __shared__ int sh[SCAN_CHUNK];
    __shared__ int sb[128];
    int b = blockIdx.x, t = threadIdx.x;

    if (t < 128) sb[t] = (t < SCAN_BLOCKS) ? d_bsum[t] : 0;
    __syncthreads();
    #pragma unroll
    for (int o = 1; o < 128; o <<= 1) {
        int x = (t < 128 && t >= o) ? sb[t - o] : 0;
        __syncthreads();
        if (t < 128) sb[t] += x;
        __syncthreads();
    }
    int base = (b > 0) ? sb[b - 1] : 0;

    int idx = b * SCAN_CHUNK + t;
    int v = (idx < NN) ? d_cnt[idx] : 0;
    sh[t] = v; __syncthreads();
    for (int o = 1; o < SCAN_CHUNK; o <<= 1) {
        int x = (t >= o) ? sh[t - o] : 0;
        __syncthreads();
        sh[t] += x;
        __syncthreads();
    }
    int excl = sh[t] - v + base;
    if (idx < NN) { d_off[idx] = excl; d_cur[idx] = excl; }
    if (idx == NN - 1) d_off[NN] = excl + v;
}

__global__ void scatter_kernel(const int* __restrict__ ei, const float* __restrict__ ea) {
    int i = blockIdx.x * blockDim.x + threadIdx.x;
    if (i < EE) {
        int dd = ei[EE + i];
        int pos = atomicAdd(&d_cur[dd], 1);
        d_csr_src[pos] = ei[i];
        d_csr_ea[pos] = ea[i];
    }
}

// ---------------- aggregation: self-term deferred; ea summed in-loop --------
__global__ void __launch_bounds__(256) agg_kernel(
    const __half2* __restrict__ xph, const float* __restrict__ asrc,
    const float* __restrict__ adst, const float* __restrict__ bias,
    float* __restrict__ hout, __half2* __restrict__ hh, int layer)
{
    int warp = (blockIdx.x * blockDim.x + threadIdx.x) >> 5;
    int lane = threadIdx.x & 31;
    if (warp >= NN) return;
    int d = warp;

    float ce = d_cedge[layer];
    int start = d_off[d];
    int end   = d_off[d + 1];
    float adst_d = adst[d];
    float asrc_d = asrc[d];
    int c = end - start;

    float2 xs = __half22float2(xph[d * 32 + lane]);
    float2 acc = make_float2(0.f, 0.f);
    float dsum = 0.f, ea_sum = 0.f;

    for (int base = start; base < end; base += 32) {
        int j = base + lane;
        float w = 0.f, eav = 0.f;
        int s = 0;
        if (j < end) {
            s = d_csr_src[j];
            eav = d_csr_ea[j];
            w = __expf(lrelu(asrc[s] + adst_d + eav * ce));
        }
        dsum += w;
        ea_sum += eav;
        int nn = min(32, end - base);
        #pragma unroll 4
        for (int jj = 0; jj < nn; jj++) {
            float wj = __shfl_sync(0xffffffff, w, jj);
            int   sj = __shfl_sync(0xffffffff, s, jj);
            float2 xv = __half22float2(xph[sj * 32 + lane]);
            acc.x += wj * xv.x;
            acc.y += wj * xv.y;
        }
    }
    #pragma unroll
    for (int o = 16; o > 0; o >>= 1) {
        dsum   += __shfl_xor_sync(0xffffffff, dsum, o);
        ea_sum += __shfl_xor_sync(0xffffffff, ea_sum, o);
    }

    // self-loop term (attr = mean of incoming edge attrs)
    float loop_ea = ea_sum / fmaxf((float)c, 1.f);
    float wself = __expf(lrelu(asrc_d + adst_d + loop_ea * ce));
    acc.x += wself * xs.x;
    acc.y += wself * xs.y;
    dsum += wself;

    float inv = 1.f / dsum;
    float ox = acc.x * inv + bias[2 * lane];
    float oy = acc.y * inv + bias[2 * lane + 1];
    if (layer == 0) {
        ox = fmaxf(ox, 0.f);
        oy = fmaxf(oy, 0.f);
        hh[d * 32 + lane] = __floats2half2_rn(ox, oy);
    } else {
        ((float2*)hout)[d * 32 + lane] = make_float2(ox, oy);
    }
}

// ---------------- pool + FC + log_softmax -----------------------------------
__device__ __forceinline__ int lowerb(const int* a, int n, int key) {
    int lo = 0, hi = n;
    while (lo < hi) {
        int mid = (lo + hi) >> 1;
        if (a[mid] < key) lo = mid + 1; else hi = mid;
    }
    return lo;
}

__global__ void __launch_bounds__(64) pool_kernel(
    const int* __restrict__ batch, const float* __restrict__ h,
    const float* __restrict__ fcW, const float* __restrict__ fcb,
    float* __restrict__ out)
{
    int g = blockIdx.x;
    int t = threadIdx.x;
    __shared__ int s_lo, s_hi;
    if (t == 0) s_lo = lowerb(batch, NN, g);
    if (t == 1) s_hi = lowerb(batch, NN, g + 1);
    __syncthreads();
    int lo = s_lo, hi = s_hi;

    float sum = 0.f;
    #pragma unroll 4
    for (int i = lo; i < hi; i++) sum += h[i * FF + t];
    float pooled = sum / fmaxf((float)(hi - lo), 1.f);

    __shared__ float P[FF];
    __shared__ float logits[OUTD];
    P[t] = pooled;
    __syncthreads();
    if (t < OUTD) {
        float acc = fcb[t];
        #pragma unroll
        for (int k = 0; k < FF; k++) acc += P[k] * fcW[t * FF + k];
        logits[t] = acc;
    }
    __syncthreads();
    if (t == 0) {
        float mx = -CUDART_INF_F;
        #pragma unroll
        for (int o = 0; o < OUTD; o++) mx = fmaxf(mx, logits[o]);
        float se = 0.f;
        #pragma unroll
        for (int o = 0; o < OUTD; o++) se += __expf(logits[o] - mx);
        float lse = mx + __logf(se);
        #pragma unroll
        for (int o = 0; o < OUTD; o++) out[g * OUTD + o] = logits[o] - lse;
    }
}

// ---------------- launch ----------------------------------------------------
extern "C" void kernel_launch(void* const* d_in, const int* in_sizes, int n_in,
                              void* d_out, int out_size) {
    const float* x    = (const float*)d_in[0];
    const int*   ei   = (const int*)  d_in[1];
    const float* ea   = (const float*)d_in[2];
    const int*   batch= (const int*)  d_in[3];
    const float* W1   = (const float*)d_in[4];
    const float* as1  = (const float*)d_in[5];
    const float* ad1  = (const float*)d_in[6];
    const float* We1  = (const float*)d_in[7];
    const float* ae1  = (const float*)d_in[8];
    const float* b1   = (const float*)d_in[9];
    const float* W2   = (const float*)d_in[10];
    const float* as2  = (const float*)d_in[11];
    const float* ad2  = (const float*)d_in[12];
    const float* We2  = (const float*)d_in[13];
    const float* ae2  = (const float*)d_in[14];
    const float* b2   = (const float*)d_in[15];
    const float* fcW  = (const float*)d_in[16];
    const float* fcb  = (const float*)d_in[17];
    float* out = (float*)d_out;
    (void)in_sizes; (void)n_in; (void)out_size;

    __half2* xh  = nullptr; cudaGetSymbolAddress((void**)&xh,  d_xh);
    __half2* xph = nullptr; cudaGetSymbolAddress((void**)&xph, d_xph);
    __half2* hh  = nullptr; cudaGetSymbolAddress((void**)&hh,  d_hh);
    float* h     = nullptr; cudaGetSymbolAddress((void**)&h,    d_h);
    float* asrc  = nullptr; cudaGetSymbolAddress((void**)&asrc, d_asrc);
    float* adst  = nullptr; cudaGetSymbolAddress((void**)&adst, d_adst);
    __half* Wh1  = nullptr; cudaGetSymbolAddress((void**)&Wh1, d_Wh1);
    __half* Wh2  = nullptr; cudaGetSymbolAddress((void**)&Wh2, d_Wh2);

    int agg_blocks = (NN * 32 + 255) / 256;

    zero_kernel<<<(NN * (FF / 2) + 255) / 256, 256>>>(x, We1, ae1, We2, ae2, W1, W2);
    // fused: lin1 + edge counting
    count_lin_kernel<<<LIN_BLOCKS + CNT_BLOCKS, 256>>>(ei, xh, Wh1, as1, ad1, xph, asrc, adst);
    scanA_kernel<<<SCAN_BLOCKS, 256>>>();
    scanC_kernel<<<SCAN_BLOCKS, SCAN_CHUNK>>>();
    scatter_kernel<<<(EE + 255) / 256, 256>>>(ei, ea);

    // layer 1 aggregation
    agg_kernel<<<agg_blocks, 256>>>(xph, asrc, adst, b1, h, hh, 0);
    // layer 2
    lin_tc_kernel<<<(NN + 63) / 64, 256>>>(hh, Wh2, as2, ad2, xph, asrc, adst);
    agg_kernel<<<agg_blocks, 256>>>(xph, asrc, adst, b2, h, hh, 1);
    // pool + fc + log_softmax
    pool_kernel<<<GG, FF>>>(batch, h, fcW, fcb, out);
}